// round 5
// baseline (speedup 1.0000x reference)
#include <cuda_runtime.h>
#include <math_constants.h>

// Problem shape (fixed by the dataset): B=32, H=16, N=1024, D=128, fp32.
#define Bc 32
#define Hc 16
#define Nc 1024
#define Dc 128
#define D4 (Dc / 4)                 // 32 float4 per row
#define NROWS (Bc * Hc * Nc)        // 524288
#define NTILES (NROWS / 32)         // 16384 (32 rows per tile)
#define NBH (Bc * Hc)               // 512
#define TILES_PER_BH 32

// Scratch (device globals; allocation forbidden).
__device__ float g_score[NROWS];        // per-row score (t . w2)   2 MB
__device__ float g_tpart[NTILES];       // per-tile t1.w1 partials  64 KB
__device__ int   g_count[NBH];          // ticket counters (zero-init, self-reset)

// ---------------------------------------------------------------------------
// Fused kernel. One block = one 32-row tile (all rows in one bh).
// LIGHT phase (all 16384 blocks): quad-per-warp scores + t1 partial.
// HEAVY phase (last-finishing block of each bh): softmax + scale whole bh,
// re-reading t from L2 (just streamed by this bh's 32 tiles).
// ---------------------------------------------------------------------------
__global__ __launch_bounds__(256)
void fused_kernel(const float* __restrict__ t1,
                  const float* __restrict__ t,
                  const int*   __restrict__ padding,
                  const float* __restrict__ w,      // [256]: w1 | w2
                  const float* __restrict__ bias,   // [1]
                  float*       __restrict__ out)
{
    __shared__ float s_score[Nc];       // heavy: scores -> exp -> factor
    __shared__ float s_red[8];
    __shared__ int   s_ticket;
    __shared__ int   s_padd;

    const int tile = blockIdx.x;
    const int bh   = tile >> 5;         // 32 tiles per bh
    const int tid  = threadIdx.x;
    const int wid  = tid >> 5;
    const int lane = tid & 31;
    const int g    = lane >> 3;
    const int sub  = lane & 7;

    // ---------------- LIGHT: one quad (4 rows) per warp ----------------
    const int row = tile * 32 + wid * 4 + g;
    const float4* trow  = reinterpret_cast<const float4*>(t)  + (size_t)row * D4;
    const float4* t1row = reinterpret_cast<const float4*>(t1) + (size_t)row * D4;
    const float4* wf    = reinterpret_cast<const float4*>(w);

    // t: default policy (want L2 residency for heavy re-read). t1: streaming.
    float4 c0 = trow[sub];
    float4 c1 = trow[sub + 8];
    float4 c2 = trow[sub + 16];
    float4 c3 = trow[sub + 24];
    float4 a0 = __ldcs(t1row + sub);
    float4 a1 = __ldcs(t1row + sub + 8);
    float4 a2 = __ldcs(t1row + sub + 16);
    float4 a3 = __ldcs(t1row + sub + 24);

    float4 u0 = wf[D4 + sub],      u1 = wf[D4 + sub + 8];
    float4 u2 = wf[D4 + sub + 16], u3 = wf[D4 + sub + 24];
    float4 v0 = wf[sub],           v1 = wf[sub + 8];
    float4 v2 = wf[sub + 16],      v3 = wf[sub + 24];

    float sc = c0.x*u0.x + c0.y*u0.y + c0.z*u0.z + c0.w*u0.w
             + c1.x*u1.x + c1.y*u1.y + c1.z*u1.z + c1.w*u1.w
             + c2.x*u2.x + c2.y*u2.y + c2.z*u2.z + c2.w*u2.w
             + c3.x*u3.x + c3.y*u3.y + c3.z*u3.z + c3.w*u3.w;

    float s1 = a0.x*v0.x + a0.y*v0.y + a0.z*v0.z + a0.w*v0.w
             + a1.x*v1.x + a1.y*v1.y + a1.z*v1.z + a1.w*v1.w
             + a2.x*v2.x + a2.y*v2.y + a2.z*v2.z + a2.w*v2.w
             + a3.x*v3.x + a3.y*v3.y + a3.z*v3.z + a3.w*v3.w;

    sc += __shfl_xor_sync(0xffffffffu, sc, 1);
    s1 += __shfl_xor_sync(0xffffffffu, s1, 1);
    sc += __shfl_xor_sync(0xffffffffu, sc, 2);
    s1 += __shfl_xor_sync(0xffffffffu, s1, 2);
    sc += __shfl_xor_sync(0xffffffffu, sc, 4);
    s1 += __shfl_xor_sync(0xffffffffu, s1, 4);
    s1 += __shfl_xor_sync(0xffffffffu, s1, 8);
    s1 += __shfl_xor_sync(0xffffffffu, s1, 16);   // full quad sum

    if (sub == 0) g_score[row] = sc;              // lanes 0,8,16,24
    if (lane == 0) s_red[wid] = s1;
    if (tid == 0) s_padd = Nc;
    // make g_score writes globally visible before the ticket increment
    __threadfence();
    __syncthreads();

    if (tid == 0) {
        float p = s_red[0] + s_red[1] + s_red[2] + s_red[3]
                + s_red[4] + s_red[5] + s_red[6] + s_red[7];
        g_tpart[tile] = p;
        __threadfence();
        s_ticket = atomicAdd(&g_count[bh], 1);
    }
    __syncthreads();

    if (s_ticket != TILES_PER_BH - 1) return;     // 31 of 32 blocks exit

    // ---------------- HEAVY: softmax + scale for the whole bh ----------------
    __threadfence();                               // acquire side

    // padd[b]
    {
        const int* pb = padding + (bh >> 4) * Nc;  // b = bh / Hc
        int local = Nc;
        #pragma unroll
        for (int n = tid; n < Nc; n += 256)
            if (pb[n] == 0) local = min(local, n);
        if (local < Nc) atomicMin(&s_padd, local);
    }

    // base = bias + sum of the 32 tile partials (fixed-order butterfly)
    if (wid == 0) {
        float v = g_tpart[bh * TILES_PER_BH + lane];
        #pragma unroll
        for (int o = 16; o > 0; o >>= 1)
            v += __shfl_xor_sync(0xffffffffu, v, o);
        if (lane == 0) s_red[0] = v;
    }
    __syncthreads();
    const float base = bias[0] + s_red[0];
    const int   padd = s_padd;

    // scores -> smem, max over valid
    const float* sc_g = g_score + bh * Nc;
    float m = -CUDART_INF_F;
    #pragma unroll
    for (int n = tid; n < Nc; n += 256) {
        float s = sc_g[n] + base;
        s_score[n] = s;
        if (n < padd) m = fmaxf(m, s);
    }
    #pragma unroll
    for (int o = 16; o > 0; o >>= 1)
        m = fmaxf(m, __shfl_xor_sync(0xffffffffu, m, o));
    __syncthreads();
    if (lane == 0) s_red[wid] = m;
    __syncthreads();
    float mx = fmaxf(fmaxf(fmaxf(s_red[0], s_red[1]), fmaxf(s_red[2], s_red[3])),
                     fmaxf(fmaxf(s_red[4], s_red[5]), fmaxf(s_red[6], s_red[7])));

    float esum = 0.f;
    #pragma unroll
    for (int n = tid; n < Nc; n += 256) {
        float e = (n < padd) ? __expf(s_score[n] - mx) : 0.f;
        s_score[n] = e;
        esum += e;
    }
    #pragma unroll
    for (int o = 16; o > 0; o >>= 1)
        esum += __shfl_xor_sync(0xffffffffu, esum, o);
    __syncthreads();
    if (lane == 0) s_red[wid] = esum;
    __syncthreads();
    float tot = s_red[0] + s_red[1] + s_red[2] + s_red[3]
              + s_red[4] + s_red[5] + s_red[6] + s_red[7];
    const float inv = (tot > 0.f) ? (1.f / tot) : 0.f;

    // factor in place: s_score[n] = attn + 1
    #pragma unroll
    for (int n = tid; n < Nc; n += 256)
        s_score[n] = fmaf(s_score[n], inv, 1.f);
    __syncthreads();

    // scale all 1024 rows of this bh: t re-read should hit L2
    const float4* tb = reinterpret_cast<const float4*>(t)   + (size_t)bh * Nc * D4;
    float4*       ob = reinterpret_cast<float4*>(out)        + (size_t)bh * Nc * D4;
    #pragma unroll 2
    for (int j = tid; j < Nc * D4; j += 1024) {    // 32 iters, ILP 4
        float4 x0 = __ldcs(tb + j);
        float4 x1 = __ldcs(tb + j + 256);
        float4 x2 = __ldcs(tb + j + 512);
        float4 x3 = __ldcs(tb + j + 768);
        float f0 = s_score[(j)       >> 5];
        float f1 = s_score[(j + 256) >> 5];
        float f2 = s_score[(j + 512) >> 5];
        float f3 = s_score[(j + 768) >> 5];
        x0.x *= f0; x0.y *= f0; x0.z *= f0; x0.w *= f0;
        x1.x *= f1; x1.y *= f1; x1.z *= f1; x1.w *= f1;
        x2.x *= f2; x2.y *= f2; x2.z *= f2; x2.w *= f2;
        x3.x *= f3; x3.y *= f3; x3.z *= f3; x3.w *= f3;
        __stcs(ob + j,       x0);
        __stcs(ob + j + 256, x1);
        __stcs(ob + j + 512, x2);
        __stcs(ob + j + 768, x3);
    }

    // self-reset the counter for the next graph replay
    if (tid == 0) atomicExch(&g_count[bh], 0);
}

extern "C" void kernel_launch(void* const* d_in, const int* in_sizes, int n_in,
                              void* d_out, int out_size)
{
    const float* t1      = (const float*)d_in[0];
    const float* t       = (const float*)d_in[1];
    const int*   padding = (const int*)d_in[2];

    const float* w = nullptr;
    for (int i = 3; i < n_in; i++)
        if (in_sizes[i] == 2 * Dc) { w = (const float*)d_in[i]; }
    const float* bias = (const float*)d_in[n_in - 1];

    fused_kernel<<<NTILES, 256>>>(t1, t, padding, w, bias, (float*)d_out);
    (void)out_size;
}

// round 6
// speedup vs baseline: 1.0720x; 1.0720x over previous
#include <cuda_runtime.h>
#include <math_constants.h>

// Problem shape (fixed by the dataset): B=32, H=16, N=1024, D=128, fp32.
#define Bc 32
#define Hc 16
#define Nc 1024
#define Dc 128
#define D4 (Dc / 4)                 // 32 float4 per row
#define NROWS (Bc * Hc * Nc)        // 524288 rows total

// Scratch (device globals; allocation is forbidden).
__device__ float g_score [NROWS];        // per-row score (t . w2)      2 MB
__device__ float g_part  [NROWS / 4];    // per-quad partial of t1 . w1 512 KB
__device__ float g_factor[NROWS];        // attn + 1                    2 MB

// ---------------------------------------------------------------------------
// Kernel A: one quad (4 consecutive rows, all within one bh) per warp.
// t is read with DEFAULT policy (retain in L2 for kernel C's re-read);
// t1 is read with __ldcs (evict-first: never needed again).
// ---------------------------------------------------------------------------
__global__ __launch_bounds__(256)
void score_kernel(const float* __restrict__ t1,
                  const float* __restrict__ t,
                  const float* __restrict__ w)      // [256]: w1 | w2
{
    const int warp  = (blockIdx.x * blockDim.x + threadIdx.x) >> 5;
    const int lane  = threadIdx.x & 31;
    const int g     = lane >> 3;
    const int sub   = lane & 7;

    const int quad = warp;                  // one quad per warp
    const int row  = quad * 4 + g;

    const float4* trow  = reinterpret_cast<const float4*>(t)  + (size_t)row * D4;
    const float4* t1row = reinterpret_cast<const float4*>(t1) + (size_t)row * D4;
    const float4* wf    = reinterpret_cast<const float4*>(w);

    float4 c0 = trow[sub];
    float4 c1 = trow[sub + 8];
    float4 c2 = trow[sub + 16];
    float4 c3 = trow[sub + 24];
    float4 a0 = __ldcs(t1row + sub);
    float4 a1 = __ldcs(t1row + sub + 8);
    float4 a2 = __ldcs(t1row + sub + 16);
    float4 a3 = __ldcs(t1row + sub + 24);

    float4 u0 = wf[D4 + sub],      u1 = wf[D4 + sub + 8];
    float4 u2 = wf[D4 + sub + 16], u3 = wf[D4 + sub + 24];
    float4 v0 = wf[sub],           v1 = wf[sub + 8];
    float4 v2 = wf[sub + 16],      v3 = wf[sub + 24];

    float sc = c0.x*u0.x + c0.y*u0.y + c0.z*u0.z + c0.w*u0.w
             + c1.x*u1.x + c1.y*u1.y + c1.z*u1.z + c1.w*u1.w
             + c2.x*u2.x + c2.y*u2.y + c2.z*u2.z + c2.w*u2.w
             + c3.x*u3.x + c3.y*u3.y + c3.z*u3.z + c3.w*u3.w;

    float s1 = a0.x*v0.x + a0.y*v0.y + a0.z*v0.z + a0.w*v0.w
             + a1.x*v1.x + a1.y*v1.y + a1.z*v1.z + a1.w*v1.w
             + a2.x*v2.x + a2.y*v2.y + a2.z*v2.z + a2.w*v2.w
             + a3.x*v3.x + a3.y*v3.y + a3.z*v3.z + a3.w*v3.w;

    // 8-lane butterfly: reduces sc to per-row total, s1 partially.
    sc += __shfl_xor_sync(0xffffffffu, sc, 1);
    s1 += __shfl_xor_sync(0xffffffffu, s1, 1);
    sc += __shfl_xor_sync(0xffffffffu, sc, 2);
    s1 += __shfl_xor_sync(0xffffffffu, s1, 2);
    sc += __shfl_xor_sync(0xffffffffu, sc, 4);
    s1 += __shfl_xor_sync(0xffffffffu, s1, 4);
    s1 += __shfl_xor_sync(0xffffffffu, s1, 8);
    s1 += __shfl_xor_sync(0xffffffffu, s1, 16);   // full quad sum

    if (sub == 0) g_score[row] = sc;       // lanes 0,8,16,24
    if (lane == 0) g_part[quad] = s1;
}

// ---------------------------------------------------------------------------
// Kernel B: one block per (b,h). Reduce quad partials -> base, compute padd,
// softmax over scores, write factor = attn + 1. (~6 MB traffic, tiny.)
// ---------------------------------------------------------------------------
__global__ __launch_bounds__(256)
void softmax_kernel(const int*   __restrict__ padding,
                    const float* __restrict__ bias)
{
    __shared__ float s_score[Nc];          // 4 KB
    __shared__ float s_red[8];
    __shared__ int   s_padd;

    const int bh   = blockIdx.x;
    const int b    = bh >> 4;              // Hc = 16
    const int tid  = threadIdx.x;
    const int wid  = tid >> 5;
    const int lane = tid & 31;

    if (tid == 0) s_padd = Nc;
    __syncthreads();

    // padd
    {
        const int* pb = padding + b * Nc;
        int local = Nc;
        #pragma unroll
        for (int n = tid; n < Nc; n += 256)
            if (pb[n] == 0) local = min(local, n);
        if (local < Nc) atomicMin(&s_padd, local);
    }

    // base = sum of 256 quad partials + bias
    float v = __ldcs(&g_part[bh * (Nc / 4) + tid]);
    #pragma unroll
    for (int o = 16; o > 0; o >>= 1) v += __shfl_xor_sync(0xffffffffu, v, o);
    if (lane == 0) s_red[wid] = v;
    __syncthreads();
    float base = bias[0];
    #pragma unroll
    for (int i = 0; i < 8; i++) base += s_red[i];
    const int padd = s_padd;

    // load scores + max over valid
    const float* sc_g = g_score + bh * Nc;
    float m = -CUDART_INF_F;
    #pragma unroll
    for (int n = tid; n < Nc; n += 256) {
        float sc = __ldcs(sc_g + n) + base;
        s_score[n] = sc;
        if (n < padd) m = fmaxf(m, sc);
    }
    #pragma unroll
    for (int o = 16; o > 0; o >>= 1)
        m = fmaxf(m, __shfl_xor_sync(0xffffffffu, m, o));
    __syncthreads();                        // reuse s_red
    if (lane == 0) s_red[wid] = m;
    __syncthreads();
    float mx = -CUDART_INF_F;
    #pragma unroll
    for (int i = 0; i < 8; i++) mx = fmaxf(mx, s_red[i]);

    float esum = 0.f;
    #pragma unroll
    for (int n = tid; n < Nc; n += 256) {
        float e = (n < padd) ? __expf(s_score[n] - mx) : 0.f;
        s_score[n] = e;
        esum += e;
    }
    #pragma unroll
    for (int o = 16; o > 0; o >>= 1)
        esum += __shfl_xor_sync(0xffffffffu, esum, o);
    __syncthreads();
    if (lane == 0) s_red[wid] = esum;
    __syncthreads();
    float tot = 0.f;
    #pragma unroll
    for (int i = 0; i < 8; i++) tot += s_red[i];
    const float inv = (tot > 0.f) ? (1.f / tot) : 0.f;

    float* fout = g_factor + bh * Nc;
    #pragma unroll
    for (int n = tid; n < Nc; n += 256)
        fout[n] = fmaf(s_score[n], inv, 1.f);
}

// ---------------------------------------------------------------------------
// Kernel C: out = t * factor[row].  Loop-free tile blocks, ILP = 4.
// Tiles are processed in REVERSE address order: score_kernel streamed t
// forwards, so L2 holds t's tail — consume it first (LIFO = cache-friendly).
// ---------------------------------------------------------------------------
__global__ __launch_bounds__(256)
void scale_kernel(const float* __restrict__ t, float* __restrict__ out)
{
    const int tile = (int)gridDim.x - 1 - (int)blockIdx.x;   // reverse order
    const size_t base = (size_t)tile * 1024;
    const int    tid  = threadIdx.x;
    const float4* tv = reinterpret_cast<const float4*>(t);
    float4* ov = reinterpret_cast<float4*>(out);

    float4 v0 = __ldcs(tv + base + tid);
    float4 v1 = __ldcs(tv + base + tid + 256);
    float4 v2 = __ldcs(tv + base + tid + 512);
    float4 v3 = __ldcs(tv + base + tid + 768);

    const int row0 = (int)(base >> 5) + (tid >> 5);
    float f0 = g_factor[row0];
    float f1 = g_factor[row0 + 8];
    float f2 = g_factor[row0 + 16];
    float f3 = g_factor[row0 + 24];

    v0.x *= f0; v0.y *= f0; v0.z *= f0; v0.w *= f0;
    v1.x *= f1; v1.y *= f1; v1.z *= f1; v1.w *= f1;
    v2.x *= f2; v2.y *= f2; v2.z *= f2; v2.w *= f2;
    v3.x *= f3; v3.y *= f3; v3.z *= f3; v3.w *= f3;

    __stcs(ov + base + tid,       v0);
    __stcs(ov + base + tid + 256, v1);
    __stcs(ov + base + tid + 512, v2);
    __stcs(ov + base + tid + 768, v3);
}

extern "C" void kernel_launch(void* const* d_in, const int* in_sizes, int n_in,
                              void* d_out, int out_size)
{
    const float* t1      = (const float*)d_in[0];
    const float* t       = (const float*)d_in[1];
    const int*   padding = (const int*)d_in[2];

    const float* w = nullptr;
    for (int i = 3; i < n_in; i++)
        if (in_sizes[i] == 2 * Dc) { w = (const float*)d_in[i]; }
    const float* bias = (const float*)d_in[n_in - 1];

    float* out = (float*)d_out;

    score_kernel<<<NROWS / 4 / 8, 256>>>(t1, t, w);
    softmax_kernel<<<Bc * Hc, 256>>>(padding, bias);
    scale_kernel<<<16384, 256>>>(t, out);
    (void)out_size;
}